// round 15
// baseline (speedup 1.0000x reference)
#include <cuda_runtime.h>
#include <cuda_bf16.h>
#include <math.h>
#include <stdint.h>

// Problem constants
#define BB 1024
#define LL 8
#define EE 256
#define RR 10000
#define RP1 10001
#define RS 10016            // padded K stride for psf/embT (mult of 32)
#define NSPLIT 18           // split-K for emb1 GEMM (tgemm2, BN=256)
#define KCH 576             // 18*576 >= 10016, mult of 32

// ------------------------- scratch (static device memory) ---------------------
__device__ float g_c[BB*EE];
__device__ float g_G[BB*4*EE];
__device__ float g_hid[BB*LL*EE];
__device__ float g_emb1[BB*EE];
__device__ float g_part[NSPLIT*BB*EE];
__device__ float g_svecs[6*EE];
__device__ float g_bsum[4*EE];
__device__ float g_plast[BB];

__device__ __nv_bfloat16 g_xh[BB*LL*EE],  g_xl[BB*LL*EE];
__device__ __nv_bfloat16 g_hh[BB*EE],     g_hl[BB*EE];
__device__ __nv_bfloat16 g_wfh[4*EE*2*EE],g_wfl[4*EE*2*EE];   // [w_hh | w_ih] fused
__device__ __nv_bfloat16 g_fc1wh[EE*2*EE],g_fc1wl[EE*2*EE];
__device__ __nv_bfloat16 g_fc2wh[(long long)RP1*EE], g_fc2wl[(long long)RP1*EE];
__device__ __nv_bfloat16 g_embTh[(long long)EE*RS],  g_embTl[(long long)EE*RS];
__device__ __nv_bfloat16 g_psfh[(long long)BB*RS],   g_psfl[(long long)BB*RS];
__device__ __nv_bfloat16 g_fc1h[BB*EE],   g_fc1l[BB*EE];
__device__ __nv_bfloat16 g_e1h[BB*EE],    g_e1l[BB*EE];

// ------------------------- PTX helpers ----------------------------------------
__device__ __forceinline__ uint32_t u32s(const void* p){
    uint32_t a;
    asm("{ .reg .u64 t; cvta.to.shared.u64 t, %1; cvt.u32.u64 %0, t; }" : "=r"(a) : "l"(p));
    return a;
}
__device__ __forceinline__ void cpa16(uint32_t dst, const void* src, uint32_t sz){
    asm volatile("cp.async.cg.shared.global [%0], [%1], 16, %2;" :: "r"(dst), "l"(src), "r"(sz));
}
__device__ __forceinline__ void cpa_commit(){ asm volatile("cp.async.commit_group;" ::: "memory"); }
__device__ __forceinline__ void ldm4(uint32_t* r, uint32_t addr){
    asm volatile("ldmatrix.sync.aligned.m8n8.x4.shared.b16 {%0,%1,%2,%3}, [%4];"
        : "=r"(r[0]), "=r"(r[1]), "=r"(r[2]), "=r"(r[3]) : "r"(addr));
}
__device__ __forceinline__ void mma_bf16(float* c, const uint32_t* a, const uint32_t* b){
    asm volatile(
        "mma.sync.aligned.m16n8k16.row.col.f32.bf16.bf16.f32 "
        "{%0,%1,%2,%3}, {%4,%5,%6,%7}, {%8,%9}, {%0,%1,%2,%3};"
        : "+f"(c[0]), "+f"(c[1]), "+f"(c[2]), "+f"(c[3])
        : "r"(a[0]), "r"(a[1]), "r"(a[2]), "r"(a[3]), "r"(b[0]), "r"(b[1]));
}
__device__ __forceinline__ void split2(float v, __nv_bfloat16& hi, __nv_bfloat16& lo){
    hi = __float2bfloat16(v);
    lo = __float2bfloat16(v - __bfloat162float(hi));
}

// ------------------------- bf16x3 NT GEMM (R7-proven, BN=128) ------------------
#define ST 3
#define TILEB 10240
#define STAGEB (4*TILEB)
#define GSMEM (ST*STAGEB)

__global__ void __launch_bounds__(512,1) tgemm(
    int M, int N, int K,
    const __nv_bfloat16* __restrict__ Ah, const __nv_bfloat16* __restrict__ Al, int lda,
    const __nv_bfloat16* __restrict__ Ah2, const __nv_bfloat16* __restrict__ Al2,
    int lda2, int kSplit,
    const __nv_bfloat16* __restrict__ Bh, const __nv_bfloat16* __restrict__ Bl, int ldb,
    float* __restrict__ C, int ldc,
    const float* __restrict__ bias,
    const float* __restrict__ add, long long addStride,
    int doRelu,
    __nv_bfloat16* __restrict__ Oh, __nv_bfloat16* __restrict__ Ol, int ldo)
{
    extern __shared__ char smem[];
    const int tid = threadIdx.x, lane = tid & 31, wid = tid >> 5;
    const int wm = wid >> 2, wn = wid & 3;
    const int m0 = blockIdx.y * 128, n0 = blockIdx.x * 128;
    const int nch = K >> 5;

    const uint32_t sb = u32s(smem);

    const int lrow = tid >> 2, lch = tid & 3;
    auto load = [&](int c){
        if (c < nch){
            uint32_t st = sb + (uint32_t)(c % ST) * STAGEB;
            int off = c * 32 + lch * 8;
            uint32_t d = st + (uint32_t)lrow * 80 + (uint32_t)lch * 16;
            {
                int gm = m0 + lrow;
                uint32_t sz = (gm < M) ? 16u : 0u;
                int gmc = (gm < M) ? gm : 0;
                const __nv_bfloat16 *ph, *pl; long long o;
                if (off < kSplit){ o = (long long)gmc * lda  + off;          ph = Ah;  pl = Al; }
                else             { o = (long long)gmc * lda2 + (off-kSplit); ph = Ah2; pl = Al2; }
                cpa16(d,         ph + o, sz);
                cpa16(d + TILEB, pl + o, sz);
            }
            {
                int gn = n0 + lrow;
                uint32_t sz = (gn < N) ? 16u : 0u;
                long long o = (long long)((gn < N) ? gn : 0) * ldb + off;
                cpa16(d + 2*TILEB, Bh + o, sz);
                cpa16(d + 3*TILEB, Bl + o, sz);
            }
        }
        cpa_commit();
    };

    const int aq = lane >> 3, ar = lane & 7;
    const uint32_t aoff = (uint32_t)((wm*32 + (aq&1)*8 + ar) * 80 + (aq>>1) * 16);
    const uint32_t boff = (uint32_t)((wn*32 + ((lane>>4)&1)*8 + ar) * 80 + ((lane>>3)&1) * 16);

    float acc[2][4][4];
    #pragma unroll
    for (int i = 0; i < 2; i++)
        #pragma unroll
        for (int j = 0; j < 4; j++)
            #pragma unroll
            for (int q = 0; q < 4; q++) acc[i][j][q] = 0.f;

    for (int c = 0; c < ST-1; c++) load(c);

    for (int c = 0; c < nch; c++){
        asm volatile("cp.async.wait_group %0;" :: "n"(ST-2) : "memory");
        __syncthreads();
        load(c + ST - 1);

        uint32_t st = sb + (uint32_t)(c % ST) * STAGEB;
        #pragma unroll
        for (int ks = 0; ks < 2; ks++){
            uint32_t Ahr[2][4], Alr[2][4], Bhr[4][2], Blr[4][2];
            #pragma unroll
            for (int i = 0; i < 2; i++){
                ldm4(Ahr[i], st + aoff + i*1280 + ks*32);
                ldm4(Alr[i], st + TILEB + aoff + i*1280 + ks*32);
            }
            #pragma unroll
            for (int p = 0; p < 2; p++){
                uint32_t t[4];
                ldm4(t, st + 2*TILEB + boff + p*1280 + ks*32);
                Bhr[2*p][0]=t[0]; Bhr[2*p][1]=t[1]; Bhr[2*p+1][0]=t[2]; Bhr[2*p+1][1]=t[3];
                ldm4(t, st + 3*TILEB + boff + p*1280 + ks*32);
                Blr[2*p][0]=t[0]; Blr[2*p][1]=t[1]; Blr[2*p+1][0]=t[2]; Blr[2*p+1][1]=t[3];
            }
            #pragma unroll
            for (int i = 0; i < 2; i++)
                #pragma unroll
                for (int j = 0; j < 4; j++){
                    mma_bf16(acc[i][j], Ahr[i], Bhr[j]);
                    mma_bf16(acc[i][j], Ahr[i], Blr[j]);
                    mma_bf16(acc[i][j], Alr[i], Bhr[j]);
                }
        }
        __syncthreads();
    }

    const int mr  = m0 + wm*32 + (lane >> 2);
    const int nc0 = n0 + wn*32 + (lane & 3)*2;

    #pragma unroll
    for (int i = 0; i < 2; i++)
        #pragma unroll
        for (int j = 0; j < 4; j++)
            #pragma unroll
            for (int h = 0; h < 2; h++){
                int m = mr + i*16 + h*8;
                #pragma unroll
                for (int e = 0; e < 2; e++){
                    int n = nc0 + j*8 + e;
                    if (n >= N) continue;
                    float v = acc[i][j][2*h + e];
                    if (bias) v += bias[n];
                    if (add)  v += add[(long long)m*addStride + n];
                    if (doRelu) v = fmaxf(v, 0.f);
                    if (C) C[(long long)m*ldc + n] = v;
                    if (Oh){
                        __nv_bfloat16 hi, lo; split2(v, hi, lo);
                        Oh[(long long)m*ldo + n] = hi;
                        Ol[(long long)m*ldo + n] = lo;
                    }
                }
            }
}

// ------------------------- bf16x3 NT GEMM2: BM=128, BN=256, 256 threads --------
// 8 warps (2 m x 4 n), 64x64 warp tiles, 192 MMAs/warp-chunk (high ILP).
// Used for fc2 (grid 40x8) and the split-K emb1 GEMM (grid 1x8xNSPLIT).
#define AT2 10240
#define BT2 20480
#define STAGE2 (2*AT2 + 2*BT2)     // 61440
#define GSMEM2 (ST*STAGE2)         // 184320

__global__ void __launch_bounds__(256,1) tgemm2(
    int M, int N, int K,
    const __nv_bfloat16* __restrict__ Ah, const __nv_bfloat16* __restrict__ Al, int lda,
    const __nv_bfloat16* __restrict__ Bh, const __nv_bfloat16* __restrict__ Bl, int ldb,
    float* __restrict__ C, int ldc,
    const float* __restrict__ bias,
    float* __restrict__ part, int kChunk)
{
    extern __shared__ char smem[];
    const int tid = threadIdx.x, lane = tid & 31, wid = tid >> 5;
    const int wm = wid >> 2, wn = wid & 3;          // 2 (m) x 4 (n)
    const int m0 = blockIdx.y * 128, n0 = blockIdx.x * 256;

    int k0 = 0, k1 = K;
    if (part){ k0 = blockIdx.z * kChunk; k1 = min(K, k0 + kChunk); }
    const int nch = (k1 - k0) >> 5;

    const uint32_t sb = u32s(smem);

    auto load = [&](int c){
        if (c < nch){
            uint32_t st = sb + (uint32_t)(c % ST) * STAGE2;
            #pragma unroll
            for (int r = 0; r < 6; r++){
                int idx = tid + r * 256;          // 0..1535
                int row = idx >> 2, ch = idx & 3;
                int off = k0 + c * 32 + ch * 8;
                if (row < 128){                    // A rows
                    int gm = m0 + row;
                    uint32_t sz = (gm < M) ? 16u : 0u;
                    long long o = (long long)((gm < M) ? gm : 0) * lda + off;
                    uint32_t d = st + (uint32_t)row * 80 + (uint32_t)ch * 16;
                    cpa16(d,       Ah + o, sz);
                    cpa16(d + AT2, Al + o, sz);
                } else {                           // B rows 0..255
                    int br = row - 128;
                    int gn = n0 + br;
                    uint32_t sz = (gn < N) ? 16u : 0u;
                    long long o = (long long)((gn < N) ? gn : 0) * ldb + off;
                    uint32_t d = st + 2*AT2 + (uint32_t)br * 80 + (uint32_t)ch * 16;
                    cpa16(d,       Bh + o, sz);
                    cpa16(d + BT2, Bl + o, sz);
                }
            }
        }
        cpa_commit();
    };

    const int aq = lane >> 3, ar = lane & 7;
    const uint32_t aoff = (uint32_t)((wm*64 + (aq&1)*8 + ar) * 80 + (aq>>1) * 16);
    const uint32_t boff = (uint32_t)(2*AT2 + (wn*64 + ((lane>>4)&1)*8 + ar) * 80
                                     + ((lane>>3)&1) * 16);

    float acc[4][8][4];
    #pragma unroll
    for (int i = 0; i < 4; i++)
        #pragma unroll
        for (int j = 0; j < 8; j++)
            #pragma unroll
            for (int q = 0; q < 4; q++) acc[i][j][q] = 0.f;

    for (int c = 0; c < ST-1; c++) load(c);

    for (int c = 0; c < nch; c++){
        asm volatile("cp.async.wait_group %0;" :: "n"(ST-2) : "memory");
        __syncthreads();
        load(c + ST - 1);

        uint32_t st = sb + (uint32_t)(c % ST) * STAGE2;
        #pragma unroll
        for (int ks = 0; ks < 2; ks++){
            uint32_t Ahr[4][4], Alr[4][4], Bhr[8][2], Blr[8][2];
            #pragma unroll
            for (int i = 0; i < 4; i++){
                ldm4(Ahr[i], st + aoff + i*1280 + ks*32);
                ldm4(Alr[i], st + AT2 + aoff + i*1280 + ks*32);
            }
            #pragma unroll
            for (int p = 0; p < 4; p++){
                uint32_t t[4];
                ldm4(t, st + boff + p*1280 + ks*32);
                Bhr[2*p][0]=t[0]; Bhr[2*p][1]=t[1]; Bhr[2*p+1][0]=t[2]; Bhr[2*p+1][1]=t[3];
                ldm4(t, st + BT2 + boff + p*1280 + ks*32);
                Blr[2*p][0]=t[0]; Blr[2*p][1]=t[1]; Blr[2*p+1][0]=t[2]; Blr[2*p+1][1]=t[3];
            }
            #pragma unroll
            for (int i = 0; i < 4; i++)
                #pragma unroll
                for (int j = 0; j < 8; j++){
                    mma_bf16(acc[i][j], Ahr[i], Bhr[j]);
                    mma_bf16(acc[i][j], Ahr[i], Blr[j]);
                    mma_bf16(acc[i][j], Alr[i], Bhr[j]);
                }
        }
        __syncthreads();
    }

    const int mr  = m0 + wm*64 + (lane >> 2);
    const int nc0 = n0 + wn*64 + (lane & 3)*2;

    if (part){
        float* P = part + (long long)blockIdx.z * M * N;
        #pragma unroll
        for (int i = 0; i < 4; i++)
            #pragma unroll
            for (int j = 0; j < 8; j++)
                #pragma unroll
                for (int h = 0; h < 2; h++){
                    int m = mr + i*16 + h*8, n = nc0 + j*8;
                    if (n < N){
                        P[(long long)m*N + n]     = acc[i][j][2*h];
                        P[(long long)m*N + n + 1] = acc[i][j][2*h+1];
                    }
                }
        return;
    }

    #pragma unroll
    for (int i = 0; i < 4; i++)
        #pragma unroll
        for (int j = 0; j < 8; j++)
            #pragma unroll
            for (int h = 0; h < 2; h++){
                int m = mr + i*16 + h*8;
                #pragma unroll
                for (int e = 0; e < 2; e++){
                    int n = nc0 + j*8 + e;
                    if (n >= N) continue;
                    float v = acc[i][j][2*h + e];
                    if (bias) v += bias[n];
                    C[(long long)m*ldc + n] = v;
                }
            }
}

// ------------------------- split-K reduce + emb1 epilogue ----------------------
__global__ void reduce_splitk(const float* __restrict__ part, float* __restrict__ emb1,
                              __nv_bfloat16* __restrict__ eh, __nv_bfloat16* __restrict__ el,
                              const float* __restrict__ hidI, const float* __restrict__ plast)
{
    int idx = blockIdx.x * blockDim.x + threadIdx.x;
    if (idx >= BB * EE) return;
    int m = idx >> 8, n = idx & 255;
    float v = 0.f;
    #pragma unroll
    for (int s = 0; s < NSPLIT; s++) v += part[(long long)s * BB * EE + idx];
    v += plast[m] * hidI[(long long)m * LL * EE + n];
    emb1[idx] = v;
    __nv_bfloat16 hi, lo; split2(v, hi, lo);
    eh[idx] = hi; el[idx] = lo;
}

// ------------------------- helper kernels --------------------------------------
__global__ void conv_kernel(const float* __restrict__ src, __nv_bfloat16* __restrict__ hi,
                            __nv_bfloat16* __restrict__ lo, int n)
{
    int i = blockIdx.x * blockDim.x + threadIdx.x;
    if (i < n){ __nv_bfloat16 h, l; split2(src[i], h, l); hi[i] = h; lo[i] = l; }
}

__global__ void fusew_kernel(const float* __restrict__ w_ih, const float* __restrict__ w_hh,
                             __nv_bfloat16* __restrict__ hi, __nv_bfloat16* __restrict__ lo)
{
    int i = blockIdx.x * blockDim.x + threadIdx.x;
    if (i >= 4*EE*2*EE) return;
    int n = i >> 9, k = i & 511;
    float v = (k < EE) ? w_hh[(long long)n*EE + k] : w_ih[(long long)n*EE + (k-EE)];
    __nv_bfloat16 h, l; split2(v, h, l);
    hi[i] = h; lo[i] = l;
}

__global__ void transpose_kernel(const float* __restrict__ src,
                                 __nv_bfloat16* __restrict__ dh, __nv_bfloat16* __restrict__ dl)
{
    __shared__ float tile[32][33];
    int r0 = blockIdx.x * 32, e0 = blockIdx.y * 32;
    for (int i = threadIdx.y; i < 32; i += 8){
        int r = r0 + i, e = e0 + threadIdx.x;
        tile[i][threadIdx.x] = (r < RR) ? src[(long long)r * EE + e] : 0.f;
    }
    __syncthreads();
    for (int i = threadIdx.y; i < 32; i += 8){
        int e = e0 + i, r = r0 + threadIdx.x;
        __nv_bfloat16 h, l; split2(tile[threadIdx.x][i], h, l);
        dh[(long long)e * RS + r] = h;
        dl[(long long)e * RS + r] = l;
    }
}

__global__ void gather_kernel(const int* __restrict__ bodys, const float* __restrict__ emb_w,
                              __nv_bfloat16* __restrict__ xh, __nv_bfloat16* __restrict__ xl)
{
    int bl = blockIdx.x;
    int r = bodys[bl];
    for (int i = threadIdx.x; i < EE; i += blockDim.x){
        __nv_bfloat16 h, l; split2(emb_w[(long long)r * EE + i], h, l);
        xh[(long long)bl * EE + i] = h;
        xl[(long long)bl * EE + i] = l;
    }
}

__global__ void bsum_kernel(const float* __restrict__ b_ih, const float* __restrict__ b_hh,
                            float* __restrict__ bsum)
{
    int i = threadIdx.x;
    if (i < 4 * EE) bsum[i] = b_ih[i] + b_hh[i];
}

__global__ void lstm_gates(const float* __restrict__ G, __nv_bfloat16* __restrict__ hh,
                           __nv_bfloat16* __restrict__ hl, float* __restrict__ c,
                           float* __restrict__ hid, int t)
{
    int idx = blockIdx.x * blockDim.x + threadIdx.x;
    if (idx >= BB * EE) return;
    int b = idx >> 8, e = idx & 255;
    const float* g = G + (long long)b * (4 * EE);
    float gi = g[e], gf = g[EE + e], gg = g[2*EE + e], go = g[3*EE + e];
    float si = 1.f / (1.f + __expf(-gi));
    float sf = 1.f / (1.f + __expf(-gf));
    float so = 1.f / (1.f + __expf(-go));
    float cp = (t == 0) ? 0.f : c[idx];
    float cn = sf * cp + si * tanhf(gg);
    c[idx] = cn;
    float hn = so * tanhf(cn);
    __nv_bfloat16 hi, lo; split2(hn, hi, lo);
    hh[idx] = hi; hl[idx] = lo;
    hid[((long long)b * LL + t) * EE + e] = hn;
}

__global__ void __launch_bounds__(256) softmax_kernel(
    const float* __restrict__ prob, __nv_bfloat16* __restrict__ ph,
    __nv_bfloat16* __restrict__ pl, float* __restrict__ plast)
{
    __shared__ float sm[RS];
    __shared__ float red[8];
    int b = blockIdx.x, tid = threadIdx.x;
    const float* x = prob + (long long)b * RP1;

    float mx = -1e30f;
    #pragma unroll
    for (int j = 0; j < 40; j++){
        int i = tid + j * 256;
        float t = -1e30f;
        if (i < RP1) t = x[i];
        if (i < RS) sm[i] = t;
        mx = fmaxf(mx, t);
    }
    #pragma unroll
    for (int o = 16; o; o >>= 1) mx = fmaxf(mx, __shfl_xor_sync(0xffffffffu, mx, o));
    if ((tid & 31) == 0) red[tid >> 5] = mx;
    __syncthreads();
    mx = red[0];
    #pragma unroll
    for (int w = 1; w < 8; w++) mx = fmaxf(mx, red[w]);
    __syncthreads();

    float s = 0.f;
    #pragma unroll
    for (int j = 0; j < 40; j++){
        int i = tid + j * 256;
        if (i < RS){
            float e = (i < RP1) ? __expf(sm[i] - mx) : 0.f;
            sm[i] = e; s += e;
        }
    }
    #pragma unroll
    for (int o = 16; o; o >>= 1) s += __shfl_xor_sync(0xffffffffu, s, o);
    __syncthreads();
    if ((tid & 31) == 0) red[tid >> 5] = s;
    __syncthreads();
    s = 0.f;
    #pragma unroll
    for (int w = 0; w < 8; w++) s += red[w];
    float inv = 1.f / s;

    __nv_bfloat162* yh2 = (__nv_bfloat162*)(ph + (long long)b * RS);
    __nv_bfloat162* yl2 = (__nv_bfloat162*)(pl + (long long)b * RS);
    const __nv_bfloat16 z = __float2bfloat16(0.f);
    #pragma unroll
    for (int j = 0; j < 20; j++){
        int p = tid + j * 256;
        if (p < RS/2){
            int i0 = 2 * p;
            __nv_bfloat16 h0, l0, h1, l1;
            if (i0 < RR){
                split2(sm[i0] * inv,     h0, l0);
                split2(sm[i0 + 1] * inv, h1, l1);
            } else {
                h0 = l0 = h1 = l1 = z;
                if (i0 == RR) plast[b] = sm[i0] * inv;
            }
            yh2[p] = __nv_bfloat162{h0, h1};
            yl2[p] = __nv_bfloat162{l0, l1};
        }
    }
}

__global__ void svec_all_kernel(const float* __restrict__ fc1_w, const float* __restrict__ fc1_b,
                                const float* __restrict__ emb_w, float* __restrict__ svecs)
{
    __shared__ float er[EE];
    int it = blockIdx.x;
    int e = threadIdx.x;
    er[e] = emb_w[(long long)(it + 2) * EE + e];
    __syncthreads();
    const float* w = fc1_w + (long long)e * (2 * EE) + EE;
    float s = fc1_b[e];
    #pragma unroll 8
    for (int k = 0; k < EE; k++) s += w[k] * er[k];
    svecs[(long long)it * EE + e] = s;
}

__global__ void concat_kernel(const float* __restrict__ emb1,
                              const float* __restrict__ emb_w, float* __restrict__ out)
{
    int idx = blockIdx.x * blockDim.x + threadIdx.x;
    if (idx >= BB * 2 * EE) return;
    int b = idx >> 9, e = idx & 511;
    out[idx] = (e < EE) ? emb1[(long long)b * EE + e]
                        : emb_w[(long long)(LL - 1) * EE + (e - EE)];
}

// ------------------------- host launch sequence --------------------------------
template<class T> static T* sym_addr(const void* s){ void* p = nullptr; cudaGetSymbolAddress(&p, s); return (T*)p; }

extern "C" void kernel_launch(void* const* d_in, const int* in_sizes, int n_in,
                              void* d_out, int out_size)
{
    const int*   bodys = (const int*)d_in[0];
    const float* emb_w = (const float*)d_in[1];
    const float* w_ih  = (const float*)d_in[2];
    const float* w_hh  = (const float*)d_in[3];
    const float* b_ih  = (const float*)d_in[4];
    const float* b_hh  = (const float*)d_in[5];
    const float* fc1_w = (const float*)d_in[6];
    const float* fc1_b = (const float*)d_in[7];
    const float* fc2_w = (const float*)d_in[8];
    const float* fc2_b = (const float*)d_in[9];

    float* prob   = (float*)d_out;
    float* outcat = prob + (long long)BB * RP1;

    float* cbuf  = sym_addr<float>(g_c);
    float* G     = sym_addr<float>(g_G);
    float* hid   = sym_addr<float>(g_hid);
    float* emb1  = sym_addr<float>(g_emb1);
    float* part  = sym_addr<float>(g_part);
    float* svecs = sym_addr<float>(g_svecs);
    float* bsum  = sym_addr<float>(g_bsum);
    float* plast = sym_addr<float>(g_plast);

    __nv_bfloat16* xh    = sym_addr<__nv_bfloat16>(g_xh);
    __nv_bfloat16* xl    = sym_addr<__nv_bfloat16>(g_xl);
    __nv_bfloat16* hh    = sym_addr<__nv_bfloat16>(g_hh);
    __nv_bfloat16* hl    = sym_addr<__nv_bfloat16>(g_hl);
    __nv_bfloat16* wfh   = sym_addr<__nv_bfloat16>(g_wfh);
    __nv_bfloat16* wfl   = sym_addr<__nv_bfloat16>(g_wfl);
    __nv_bfloat16* fc1wh = sym_addr<__nv_bfloat16>(g_fc1wh);
    __nv_bfloat16* fc1wl = sym_addr<__nv_bfloat16>(g_fc1wl);
    __nv_bfloat16* fc2wh = sym_addr<__nv_bfloat16>(g_fc2wh);
    __nv_bfloat16* fc2wl = sym_addr<__nv_bfloat16>(g_fc2wl);
    __nv_bfloat16* embTh = sym_addr<__nv_bfloat16>(g_embTh);
    __nv_bfloat16* embTl = sym_addr<__nv_bfloat16>(g_embTl);
    __nv_bfloat16* psfh  = sym_addr<__nv_bfloat16>(g_psfh);
    __nv_bfloat16* psfl  = sym_addr<__nv_bfloat16>(g_psfl);
    __nv_bfloat16* fc1h  = sym_addr<__nv_bfloat16>(g_fc1h);
    __nv_bfloat16* fc1l  = sym_addr<__nv_bfloat16>(g_fc1l);
    __nv_bfloat16* e1h   = sym_addr<__nv_bfloat16>(g_e1h);
    __nv_bfloat16* e1l   = sym_addr<__nv_bfloat16>(g_e1l);

    const __nv_bfloat16* nbf = (const __nv_bfloat16*)nullptr;
    __nv_bfloat16* nbm = (__nv_bfloat16*)nullptr;
    const float* nf = (const float*)nullptr;

    static cudaStream_t s2 = nullptr, s3 = nullptr;
    static cudaEvent_t evF = nullptr, evG = nullptr, evL = nullptr, evP = nullptr;
    if (!s2){
        cudaStreamCreateWithFlags(&s2, cudaStreamNonBlocking);
        cudaStreamCreateWithFlags(&s3, cudaStreamNonBlocking);
        cudaEventCreateWithFlags(&evF, cudaEventDisableTiming);
        cudaEventCreateWithFlags(&evG, cudaEventDisableTiming);
        cudaEventCreateWithFlags(&evL, cudaEventDisableTiming);
        cudaEventCreateWithFlags(&evP, cudaEventDisableTiming);
    }

    cudaFuncSetAttribute(tgemm,  cudaFuncAttributeMaxDynamicSharedMemorySize, GSMEM);
    cudaFuncSetAttribute(tgemm2, cudaFuncAttributeMaxDynamicSharedMemorySize, GSMEM2);

    // ---- fork s3 from the origin stream FIRST (required for graph capture)
    cudaEventRecord(evF, 0);
    cudaStreamWaitEvent(s3, evF, 0);

    // ---- stream s3: input-only prologue -- fc2 weights, embT, svecs
    conv_kernel<<<(RP1*EE + 255)/256, 256, 0, s3>>>(fc2_w, fc2wh, fc2wl, RP1*EE);
    transpose_kernel<<<dim3(RS/32, EE/32), dim3(32, 8), 0, s3>>>(emb_w, embTh, embTl);
    svec_all_kernel<<<6, EE, 0, s3>>>(fc1_w, fc1_b, emb_w, svecs);
    cudaEventRecord(evP, s3);

    // ---- main stream: gather (needed by both branches), then fork s2
    gather_kernel<<<BB*LL, 64>>>(bodys, emb_w, xh, xl);
    cudaEventRecord(evG, 0);
    cudaStreamWaitEvent(s2, evG, 0);

    // ---- side stream s2: LSTM branch
    fusew_kernel<<<(4*EE*2*EE + 255)/256, 256, 0, s2>>>(w_ih, w_hh, wfh, wfl);
    bsum_kernel<<<1, 4*EE, 0, s2>>>(b_ih, b_hh, bsum);
    for (int t = 0; t < LL; t++){
        if (t == 0){
            tgemm<<<dim3(8, 8), 512, GSMEM, s2>>>(
                BB, 4*EE, EE,
                xh, xl, LL*EE, nbf, nbf, 0, EE,
                wfh + EE, wfl + EE, 2*EE,
                G, 4*EE, bsum, nf, 0, 0,
                nbm, nbm, 0);
        } else {
            tgemm<<<dim3(8, 8), 512, GSMEM, s2>>>(
                BB, 4*EE, 2*EE,
                hh, hl, EE,
                xh + (long long)t*EE, xl + (long long)t*EE, LL*EE, EE,
                wfh, wfl, 2*EE,
                G, 4*EE, bsum, nf, 0, 0,
                nbm, nbm, 0);
        }
        lstm_gates<<<(BB*EE + 255)/256, 256, 0, s2>>>(G, hh, hl, cbuf, hid, t);
    }
    cudaEventRecord(evL, s2);

    // ---- main stream: iteration 0
    conv_kernel<<<(EE*2*EE + 255)/256, 256>>>(fc1_w, fc1wh, fc1wl, EE*2*EE);
    tgemm<<<dim3(2, 8), 512, GSMEM>>>(
        BB, EE, 2*EE, xh, xl, LL*EE, nbf, nbf, 0, 2*EE,
        fc1wh, fc1wl, 2*EE,
        (float*)nullptr, 0, fc1_b, nf, 0, 1,
        fc1h, fc1l, EE);
    cudaStreamWaitEvent(0, evP, 0);
    tgemm2<<<dim3((RP1 + 255)/256, 8), 256, GSMEM2>>>(
        BB, RP1, EE, fc1h, fc1l, EE, fc2wh, fc2wl, EE,
        prob, RP1, fc2_b, (float*)nullptr, 0);
    softmax_kernel<<<BB, 256>>>(prob, psfh, psfl, plast);

    // ---- iterations 1..6
    for (int i = 1; i < LL - 1; i++){
        tgemm2<<<dim3(1, 8, NSPLIT), 256, GSMEM2>>>(
            BB, EE, RS, psfh, psfl, RS, embTh, embTl, RS,
            (float*)nullptr, 0, nf, part, KCH);

        if (i == 1) cudaStreamWaitEvent(0, evL, 0);   // join LSTM branch

        reduce_splitk<<<(BB*EE + 255)/256, 256>>>(
            part, emb1, e1h, e1l, hid + (long long)i*EE, plast);

        tgemm<<<dim3(2, 8), 512, GSMEM>>>(
            BB, EE, EE, e1h, e1l, EE, nbf, nbf, 0, EE,
            fc1wh, fc1wl, 2*EE,
            (float*)nullptr, 0, svecs + (long long)(i-1)*EE, nf, 0, 1,
            fc1h, fc1l, EE);

        tgemm2<<<dim3((RP1 + 255)/256, 8), 256, GSMEM2>>>(
            BB, RP1, EE, fc1h, fc1l, EE, fc2wh, fc2wl, EE,
            prob, RP1, fc2_b, (float*)nullptr, 0);

        if (i < LL - 2) softmax_kernel<<<BB, 256>>>(prob, psfh, psfl, plast);
    }

    if (out_size >= BB * RP1 + BB * 2 * EE)
        concat_kernel<<<(BB*2*EE + 255)/256, 256>>>(emb1, emb_w, outcat);
}

// round 16
// speedup vs baseline: 1.0986x; 1.0986x over previous
#include <cuda_runtime.h>
#include <cuda_bf16.h>
#include <math.h>
#include <stdint.h>

// Problem constants
#define BB 1024
#define LL 8
#define EE 256
#define RR 10000
#define RP1 10001
#define RS 10016            // padded K stride for psf/embT (mult of 32)
#define NSPLIT 9
#define KCH 1120            // split-K chunk (mult of 32); 9*1120 >= 10016

// ------------------------- scratch (static device memory) ---------------------
__device__ float g_c[BB*EE];
__device__ float g_G[BB*4*EE];
__device__ float g_hid[BB*LL*EE];
__device__ float g_emb1[BB*EE];
__device__ float g_part[NSPLIT*BB*EE];
__device__ float g_svecs[6*EE];
__device__ float g_bsum[4*EE];
__device__ float g_plast[BB];

__device__ __nv_bfloat16 g_xh[BB*LL*EE],  g_xl[BB*LL*EE];
__device__ __nv_bfloat16 g_hh[BB*EE],     g_hl[BB*EE];
__device__ __nv_bfloat16 g_wfh[4*EE*2*EE],g_wfl[4*EE*2*EE];   // [w_hh | w_ih] fused
__device__ __nv_bfloat16 g_fc1wh[EE*2*EE],g_fc1wl[EE*2*EE];
__device__ __nv_bfloat16 g_fc2wh[(long long)RP1*EE], g_fc2wl[(long long)RP1*EE];
__device__ __nv_bfloat16 g_embTh[(long long)EE*RS],  g_embTl[(long long)EE*RS];
__device__ __nv_bfloat16 g_psfh[(long long)BB*RS],   g_psfl[(long long)BB*RS];
__device__ __nv_bfloat16 g_fc1h[BB*EE],   g_fc1l[BB*EE];
__device__ __nv_bfloat16 g_e1h[BB*EE],    g_e1l[BB*EE];

// ------------------------- PTX helpers ----------------------------------------
__device__ __forceinline__ uint32_t u32s(const void* p){
    uint32_t a;
    asm("{ .reg .u64 t; cvta.to.shared.u64 t, %1; cvt.u32.u64 %0, t; }" : "=r"(a) : "l"(p));
    return a;
}
__device__ __forceinline__ void cpa16(uint32_t dst, const void* src, uint32_t sz){
    asm volatile("cp.async.cg.shared.global [%0], [%1], 16, %2;" :: "r"(dst), "l"(src), "r"(sz));
}
__device__ __forceinline__ void cpa_commit(){ asm volatile("cp.async.commit_group;" ::: "memory"); }
__device__ __forceinline__ void ldm4(uint32_t* r, uint32_t addr){
    asm volatile("ldmatrix.sync.aligned.m8n8.x4.shared.b16 {%0,%1,%2,%3}, [%4];"
        : "=r"(r[0]), "=r"(r[1]), "=r"(r[2]), "=r"(r[3]) : "r"(addr));
}
__device__ __forceinline__ void mma_bf16(float* c, const uint32_t* a, const uint32_t* b){
    asm volatile(
        "mma.sync.aligned.m16n8k16.row.col.f32.bf16.bf16.f32 "
        "{%0,%1,%2,%3}, {%4,%5,%6,%7}, {%8,%9}, {%0,%1,%2,%3};"
        : "+f"(c[0]), "+f"(c[1]), "+f"(c[2]), "+f"(c[3])
        : "r"(a[0]), "r"(a[1]), "r"(a[2]), "r"(a[3]), "r"(b[0]), "r"(b[1]));
}
__device__ __forceinline__ void split2(float v, __nv_bfloat16& hi, __nv_bfloat16& lo){
    hi = __float2bfloat16(v);
    lo = __float2bfloat16(v - __bfloat162float(hi));
}

// ------------------------- bf16x3 NT GEMM (R7-proven, BN=128, 512 thr) ---------
#define ST 3
#define TILEB 10240
#define STAGEB (4*TILEB)
#define GSMEM (ST*STAGEB)

__global__ void __launch_bounds__(512,1) tgemm(
    int M, int N, int K,
    const __nv_bfloat16* __restrict__ Ah, const __nv_bfloat16* __restrict__ Al, int lda,
    const __nv_bfloat16* __restrict__ Ah2, const __nv_bfloat16* __restrict__ Al2,
    int lda2, int kSplit,
    const __nv_bfloat16* __restrict__ Bh, const __nv_bfloat16* __restrict__ Bl, int ldb,
    float* __restrict__ C, int ldc,
    const float* __restrict__ bias,
    const float* __restrict__ add, long long addStride,
    int doRelu,
    __nv_bfloat16* __restrict__ Oh, __nv_bfloat16* __restrict__ Ol, int ldo)
{
    extern __shared__ char smem[];
    const int tid = threadIdx.x, lane = tid & 31, wid = tid >> 5;
    const int wm = wid >> 2, wn = wid & 3;      // 4 (m) x 4 (n) warps
    const int m0 = blockIdx.y * 128, n0 = blockIdx.x * 128;
    const int nch = K >> 5;

    const uint32_t sb = u32s(smem);

    const int lrow = tid >> 2, lch = tid & 3;
    auto load = [&](int c){
        if (c < nch){
            uint32_t st = sb + (uint32_t)(c % ST) * STAGEB;
            int off = c * 32 + lch * 8;
            uint32_t d = st + (uint32_t)lrow * 80 + (uint32_t)lch * 16;
            {   // A hi/lo (dual-pointer on kSplit)
                int gm = m0 + lrow;
                uint32_t sz = (gm < M) ? 16u : 0u;
                int gmc = (gm < M) ? gm : 0;
                const __nv_bfloat16 *ph, *pl; long long o;
                if (off < kSplit){ o = (long long)gmc * lda  + off;          ph = Ah;  pl = Al; }
                else             { o = (long long)gmc * lda2 + (off-kSplit); ph = Ah2; pl = Al2; }
                cpa16(d,         ph + o, sz);
                cpa16(d + TILEB, pl + o, sz);
            }
            {   // B hi/lo
                int gn = n0 + lrow;
                uint32_t sz = (gn < N) ? 16u : 0u;
                long long o = (long long)((gn < N) ? gn : 0) * ldb + off;
                cpa16(d + 2*TILEB, Bh + o, sz);
                cpa16(d + 3*TILEB, Bl + o, sz);
            }
        }
        cpa_commit();
    };

    const int aq = lane >> 3, ar = lane & 7;
    const uint32_t aoff = (uint32_t)((wm*32 + (aq&1)*8 + ar) * 80 + (aq>>1) * 16);
    const uint32_t boff = (uint32_t)((wn*32 + ((lane>>4)&1)*8 + ar) * 80 + ((lane>>3)&1) * 16);

    float acc[2][4][4];
    #pragma unroll
    for (int i = 0; i < 2; i++)
        #pragma unroll
        for (int j = 0; j < 4; j++)
            #pragma unroll
            for (int q = 0; q < 4; q++) acc[i][j][q] = 0.f;

    for (int c = 0; c < ST-1; c++) load(c);

    for (int c = 0; c < nch; c++){
        asm volatile("cp.async.wait_group %0;" :: "n"(ST-2) : "memory");
        __syncthreads();
        load(c + ST - 1);

        uint32_t st = sb + (uint32_t)(c % ST) * STAGEB;
        #pragma unroll
        for (int ks = 0; ks < 2; ks++){
            uint32_t Ahr[2][4], Alr[2][4], Bhr[4][2], Blr[4][2];
            #pragma unroll
            for (int i = 0; i < 2; i++){
                ldm4(Ahr[i], st + aoff + i*1280 + ks*32);
                ldm4(Alr[i], st + TILEB + aoff + i*1280 + ks*32);
            }
            #pragma unroll
            for (int p = 0; p < 2; p++){
                uint32_t t[4];
                ldm4(t, st + 2*TILEB + boff + p*1280 + ks*32);
                Bhr[2*p][0]=t[0]; Bhr[2*p][1]=t[1]; Bhr[2*p+1][0]=t[2]; Bhr[2*p+1][1]=t[3];
                ldm4(t, st + 3*TILEB + boff + p*1280 + ks*32);
                Blr[2*p][0]=t[0]; Blr[2*p][1]=t[1]; Blr[2*p+1][0]=t[2]; Blr[2*p+1][1]=t[3];
            }
            #pragma unroll
            for (int i = 0; i < 2; i++)
                #pragma unroll
                for (int j = 0; j < 4; j++){
                    mma_bf16(acc[i][j], Ahr[i], Bhr[j]);
                    mma_bf16(acc[i][j], Ahr[i], Blr[j]);
                    mma_bf16(acc[i][j], Alr[i], Bhr[j]);
                }
        }
        __syncthreads();
    }

    const int mr  = m0 + wm*32 + (lane >> 2);
    const int nc0 = n0 + wn*32 + (lane & 3)*2;

    #pragma unroll
    for (int i = 0; i < 2; i++)
        #pragma unroll
        for (int j = 0; j < 4; j++)
            #pragma unroll
            for (int h = 0; h < 2; h++){
                int m = mr + i*16 + h*8;
                #pragma unroll
                for (int e = 0; e < 2; e++){
                    int n = nc0 + j*8 + e;
                    if (n >= N) continue;
                    float v = acc[i][j][2*h + e];
                    if (bias) v += bias[n];
                    if (add)  v += add[(long long)m*addStride + n];
                    if (doRelu) v = fmaxf(v, 0.f);
                    if (C) C[(long long)m*ldc + n] = v;
                    if (Oh){
                        __nv_bfloat16 hi, lo; split2(v, hi, lo);
                        Oh[(long long)m*ldo + n] = hi;
                        Ol[(long long)m*ldo + n] = lo;
                    }
                }
            }
}

// ------------------------- bf16x3 NT GEMM3: BM=64, BN=128, 256 thr, 2 CTA/SM ---
// Same per-warp workload as tgemm (24 MMAs + 12 ldm4 per ks-half), half the CTA.
// 2 co-resident CTAs hide each other's barrier/LDSM/cp.async stalls.
#define AT3 5120                       // A tile: 64 rows x 80 B
#define BT3 10240                      // B tile: 128 rows x 80 B
#define STAGE3 (2*AT3 + 2*BT3)         // 30720
#define GSMEM3 (ST*STAGE3)             // 92160

__global__ void __launch_bounds__(256,2) tgemm3(
    int M, int N, int K,
    const __nv_bfloat16* __restrict__ Ah, const __nv_bfloat16* __restrict__ Al, int lda,
    const __nv_bfloat16* __restrict__ Bh, const __nv_bfloat16* __restrict__ Bl, int ldb,
    float* __restrict__ C, int ldc,
    const float* __restrict__ bias,
    float* __restrict__ part, int kChunk)
{
    extern __shared__ char smem[];
    const int tid = threadIdx.x, lane = tid & 31, wid = tid >> 5;
    const int wm = wid >> 2, wn = wid & 3;      // 2 (m) x 4 (n)
    const int m0 = blockIdx.y * 64, n0 = blockIdx.x * 128;

    int k0 = 0, k1 = K;
    if (part){ k0 = blockIdx.z * kChunk; k1 = min(K, k0 + kChunk); }
    const int nch = (k1 - k0) >> 5;

    const uint32_t sb = u32s(smem);

    const int lrow = tid >> 2, lch = tid & 3;   // A: 64 rows x 4 chunks = 256 slots
    auto load = [&](int c){
        if (c < nch){
            uint32_t st = sb + (uint32_t)(c % ST) * STAGE3;
            int off = k0 + c * 32 + lch * 8;
            {   // A hi/lo (rows 0..63)
                int gm = m0 + lrow;
                uint32_t sz = (gm < M) ? 16u : 0u;
                long long o = (long long)((gm < M) ? gm : 0) * lda + off;
                uint32_t d = st + (uint32_t)lrow * 80 + (uint32_t)lch * 16;
                cpa16(d,       Ah + o, sz);
                cpa16(d + AT3, Al + o, sz);
            }
            #pragma unroll
            for (int r = 0; r < 2; r++){        // B: 128 rows x 4 chunks = 512 slots
                int idx = tid + r * 256;
                int row = idx >> 2, ch = idx & 3;
                int offb = k0 + c * 32 + ch * 8;
                int gn = n0 + row;
                uint32_t sz = (gn < N) ? 16u : 0u;
                long long o = (long long)((gn < N) ? gn : 0) * ldb + offb;
                uint32_t d = st + 2*AT3 + (uint32_t)row * 80 + (uint32_t)ch * 16;
                cpa16(d,       Bh + o, sz);
                cpa16(d + BT3, Bl + o, sz);
            }
        }
        cpa_commit();
    };

    const int aq = lane >> 3, ar = lane & 7;
    const uint32_t aoff = (uint32_t)((wm*32 + (aq&1)*8 + ar) * 80 + (aq>>1) * 16);
    const uint32_t boff = (uint32_t)(2*AT3 + (wn*32 + ((lane>>4)&1)*8 + ar) * 80
                                     + ((lane>>3)&1) * 16);

    float acc[2][4][4];
    #pragma unroll
    for (int i = 0; i < 2; i++)
        #pragma unroll
        for (int j = 0; j < 4; j++)
            #pragma unroll
            for (int q = 0; q < 4; q++) acc[i][j][q] = 0.f;

    for (int c = 0; c < ST-1; c++) load(c);

    for (int c = 0; c < nch; c++){
        asm volatile("cp.async.wait_group %0;" :: "n"(ST-2) : "memory");
        __syncthreads();
        load(c + ST - 1);

        uint32_t st = sb + (uint32_t)(c % ST) * STAGE3;
        #pragma unroll
        for (int ks = 0; ks < 2; ks++){
            uint32_t Ahr[2][4], Alr[2][4], Bhr[4][2], Blr[4][2];
            #pragma unroll
            for (int i = 0; i < 2; i++){
                ldm4(Ahr[i], st + aoff + i*1280 + ks*32);
                ldm4(Alr[i], st + AT3 + aoff + i*1280 + ks*32);
            }
            #pragma unroll
            for (int p = 0; p < 2; p++){
                uint32_t t[4];
                ldm4(t, st + boff + p*1280 + ks*32);
                Bhr[2*p][0]=t[0]; Bhr[2*p][1]=t[1]; Bhr[2*p+1][0]=t[2]; Bhr[2*p+1][1]=t[3];
                ldm4(t, st + BT3 + boff + p*1280 + ks*32);
                Blr[2*p][0]=t[0]; Blr[2*p][1]=t[1]; Blr[2*p+1][0]=t[2]; Blr[2*p+1][1]=t[3];
            }
            #pragma unroll
            for (int i = 0; i < 2; i++)
                #pragma unroll
                for (int j = 0; j < 4; j++){
                    mma_bf16(acc[i][j], Ahr[i], Bhr[j]);
                    mma_bf16(acc[i][j], Ahr[i], Blr[j]);
                    mma_bf16(acc[i][j], Alr[i], Bhr[j]);
                }
        }
        __syncthreads();
    }

    // NOTE: warp m-tile is 32 rows = frags i*16; wm*32 spans the 64-row block.
    const int mr  = m0 + wm*32 + (lane >> 2);
    const int nc0 = n0 + wn*32 + (lane & 3)*2;

    if (part){
        float* P = part + (long long)blockIdx.z * M * N;
        #pragma unroll
        for (int i = 0; i < 2; i++)
            #pragma unroll
            for (int j = 0; j < 4; j++)
                #pragma unroll
                for (int h = 0; h < 2; h++){
                    int m = mr + i*16 + h*8, n = nc0 + j*8;
                    if (n < N){
                        P[(long long)m*N + n]     = acc[i][j][2*h];
                        P[(long long)m*N + n + 1] = acc[i][j][2*h+1];
                    }
                }
        return;
    }

    #pragma unroll
    for (int i = 0; i < 2; i++)
        #pragma unroll
        for (int j = 0; j < 4; j++)
            #pragma unroll
            for (int h = 0; h < 2; h++){
                int m = mr + i*16 + h*8;
                #pragma unroll
                for (int e = 0; e < 2; e++){
                    int n = nc0 + j*8 + e;
                    if (n >= N) continue;
                    float v = acc[i][j][2*h + e];
                    if (bias) v += bias[n];
                    C[(long long)m*ldc + n] = v;
                }
            }
}

// ------------------------- split-K reduce + emb1 epilogue ----------------------
__global__ void reduce_splitk(const float* __restrict__ part, float* __restrict__ emb1,
                              __nv_bfloat16* __restrict__ eh, __nv_bfloat16* __restrict__ el,
                              const float* __restrict__ hidI, const float* __restrict__ plast)
{
    int idx = blockIdx.x * blockDim.x + threadIdx.x;
    if (idx >= BB * EE) return;
    int m = idx >> 8, n = idx & 255;
    float v = 0.f;
    #pragma unroll
    for (int s = 0; s < NSPLIT; s++) v += part[(long long)s * BB * EE + idx];
    v += plast[m] * hidI[(long long)m * LL * EE + n];
    emb1[idx] = v;
    __nv_bfloat16 hi, lo; split2(v, hi, lo);
    eh[idx] = hi; el[idx] = lo;
}

// ------------------------- helper kernels --------------------------------------
__global__ void conv_kernel(const float* __restrict__ src, __nv_bfloat16* __restrict__ hi,
                            __nv_bfloat16* __restrict__ lo, int n)
{
    int i = blockIdx.x * blockDim.x + threadIdx.x;
    if (i < n){ __nv_bfloat16 h, l; split2(src[i], h, l); hi[i] = h; lo[i] = l; }
}

__global__ void fusew_kernel(const float* __restrict__ w_ih, const float* __restrict__ w_hh,
                             __nv_bfloat16* __restrict__ hi, __nv_bfloat16* __restrict__ lo)
{
    int i = blockIdx.x * blockDim.x + threadIdx.x;
    if (i >= 4*EE*2*EE) return;
    int n = i >> 9, k = i & 511;
    float v = (k < EE) ? w_hh[(long long)n*EE + k] : w_ih[(long long)n*EE + (k-EE)];
    __nv_bfloat16 h, l; split2(v, h, l);
    hi[i] = h; lo[i] = l;
}

__global__ void transpose_kernel(const float* __restrict__ src,
                                 __nv_bfloat16* __restrict__ dh, __nv_bfloat16* __restrict__ dl)
{
    __shared__ float tile[32][33];
    int r0 = blockIdx.x * 32, e0 = blockIdx.y * 32;
    for (int i = threadIdx.y; i < 32; i += 8){
        int r = r0 + i, e = e0 + threadIdx.x;
        tile[i][threadIdx.x] = (r < RR) ? src[(long long)r * EE + e] : 0.f;
    }
    __syncthreads();
    for (int i = threadIdx.y; i < 32; i += 8){
        int e = e0 + i, r = r0 + threadIdx.x;
        __nv_bfloat16 h, l; split2(tile[threadIdx.x][i], h, l);
        dh[(long long)e * RS + r] = h;
        dl[(long long)e * RS + r] = l;
    }
}

__global__ void gather_kernel(const int* __restrict__ bodys, const float* __restrict__ emb_w,
                              __nv_bfloat16* __restrict__ xh, __nv_bfloat16* __restrict__ xl)
{
    int bl = blockIdx.x;
    int r = bodys[bl];
    for (int i = threadIdx.x; i < EE; i += blockDim.x){
        __nv_bfloat16 h, l; split2(emb_w[(long long)r * EE + i], h, l);
        xh[(long long)bl * EE + i] = h;
        xl[(long long)bl * EE + i] = l;
    }
}

__global__ void bsum_kernel(const float* __restrict__ b_ih, const float* __restrict__ b_hh,
                            float* __restrict__ bsum)
{
    int i = threadIdx.x;
    if (i < 4 * EE) bsum[i] = b_ih[i] + b_hh[i];
}

__global__ void lstm_gates(const float* __restrict__ G, __nv_bfloat16* __restrict__ hh,
                           __nv_bfloat16* __restrict__ hl, float* __restrict__ c,
                           float* __restrict__ hid, int t)
{
    int idx = blockIdx.x * blockDim.x + threadIdx.x;
    if (idx >= BB * EE) return;
    int b = idx >> 8, e = idx & 255;
    const float* g = G + (long long)b * (4 * EE);
    float gi = g[e], gf = g[EE + e], gg = g[2*EE + e], go = g[3*EE + e];
    float si = 1.f / (1.f + __expf(-gi));
    float sf = 1.f / (1.f + __expf(-gf));
    float so = 1.f / (1.f + __expf(-go));
    float cp = (t == 0) ? 0.f : c[idx];
    float cn = sf * cp + si * tanhf(gg);
    c[idx] = cn;
    float hn = so * tanhf(cn);
    __nv_bfloat16 hi, lo; split2(hn, hi, lo);
    hh[idx] = hi; hl[idx] = lo;
    hid[((long long)b * LL + t) * EE + e] = hn;
}

__global__ void __launch_bounds__(256) softmax_kernel(
    const float* __restrict__ prob, __nv_bfloat16* __restrict__ ph,
    __nv_bfloat16* __restrict__ pl, float* __restrict__ plast)
{
    __shared__ float sm[RS];
    __shared__ float red[8];
    int b = blockIdx.x, tid = threadIdx.x;
    const float* x = prob + (long long)b * RP1;

    float mx = -1e30f;
    #pragma unroll
    for (int j = 0; j < 40; j++){
        int i = tid + j * 256;
        float t = -1e30f;
        if (i < RP1) t = x[i];
        if (i < RS) sm[i] = t;
        mx = fmaxf(mx, t);
    }
    #pragma unroll
    for (int o = 16; o; o >>= 1) mx = fmaxf(mx, __shfl_xor_sync(0xffffffffu, mx, o));
    if ((tid & 31) == 0) red[tid >> 5] = mx;
    __syncthreads();
    mx = red[0];
    #pragma unroll
    for (int w = 1; w < 8; w++) mx = fmaxf(mx, red[w]);
    __syncthreads();

    float s = 0.f;
    #pragma unroll
    for (int j = 0; j < 40; j++){
        int i = tid + j * 256;
        if (i < RS){
            float e = (i < RP1) ? __expf(sm[i] - mx) : 0.f;
            sm[i] = e; s += e;
        }
    }
    #pragma unroll
    for (int o = 16; o; o >>= 1) s += __shfl_xor_sync(0xffffffffu, s, o);
    __syncthreads();
    if ((tid & 31) == 0) red[tid >> 5] = s;
    __syncthreads();
    s = 0.f;
    #pragma unroll
    for (int w = 0; w < 8; w++) s += red[w];
    float inv = 1.f / s;

    __nv_bfloat162* yh2 = (__nv_bfloat162*)(ph + (long long)b * RS);
    __nv_bfloat162* yl2 = (__nv_bfloat162*)(pl + (long long)b * RS);
    const __nv_bfloat16 z = __float2bfloat16(0.f);
    #pragma unroll
    for (int j = 0; j < 20; j++){
        int p = tid + j * 256;
        if (p < RS/2){
            int i0 = 2 * p;
            __nv_bfloat16 h0, l0, h1, l1;
            if (i0 < RR){
                split2(sm[i0] * inv,     h0, l0);
                split2(sm[i0 + 1] * inv, h1, l1);
            } else {
                h0 = l0 = h1 = l1 = z;
                if (i0 == RR) plast[b] = sm[i0] * inv;
            }
            yh2[p] = __nv_bfloat162{h0, h1};
            yl2[p] = __nv_bfloat162{l0, l1};
        }
    }
}

__global__ void svec_all_kernel(const float* __restrict__ fc1_w, const float* __restrict__ fc1_b,
                                const float* __restrict__ emb_w, float* __restrict__ svecs)
{
    __shared__ float er[EE];
    int it = blockIdx.x;
    int e = threadIdx.x;
    er[e] = emb_w[(long long)(it + 2) * EE + e];
    __syncthreads();
    const float* w = fc1_w + (long long)e * (2 * EE) + EE;
    float s = fc1_b[e];
    #pragma unroll 8
    for (int k = 0; k < EE; k++) s += w[k] * er[k];
    svecs[(long long)it * EE + e] = s;
}

__global__ void concat_kernel(const float* __restrict__ emb1,
                              const float* __restrict__ emb_w, float* __restrict__ out)
{
    int idx = blockIdx.x * blockDim.x + threadIdx.x;
    if (idx >= BB * 2 * EE) return;
    int b = idx >> 9, e = idx & 511;
    out[idx] = (e < EE) ? emb1[(long long)b * EE + e]
                        : emb_w[(long long)(LL - 1) * EE + (e - EE)];
}

// ------------------------- host launch sequence --------------------------------
template<class T> static T* sym_addr(const void* s){ void* p = nullptr; cudaGetSymbolAddress(&p, s); return (T*)p; }

extern "C" void kernel_launch(void* const* d_in, const int* in_sizes, int n_in,
                              void* d_out, int out_size)
{
    const int*   bodys = (const int*)d_in[0];
    const float* emb_w = (const float*)d_in[1];
    const float* w_ih  = (const float*)d_in[2];
    const float* w_hh  = (const float*)d_in[3];
    const float* b_ih  = (const float*)d_in[4];
    const float* b_hh  = (const float*)d_in[5];
    const float* fc1_w = (const float*)d_in[6];
    const float* fc1_b = (const float*)d_in[7];
    const float* fc2_w = (const float*)d_in[8];
    const float* fc2_b = (const float*)d_in[9];

    float* prob   = (float*)d_out;
    float* outcat = prob + (long long)BB * RP1;

    float* cbuf  = sym_addr<float>(g_c);
    float* G     = sym_addr<float>(g_G);
    float* hid   = sym_addr<float>(g_hid);
    float* emb1  = sym_addr<float>(g_emb1);
    float* part  = sym_addr<float>(g_part);
    float* svecs = sym_addr<float>(g_svecs);
    float* bsum  = sym_addr<float>(g_bsum);
    float* plast = sym_addr<float>(g_plast);

    __nv_bfloat16* xh    = sym_addr<__nv_bfloat16>(g_xh);
    __nv_bfloat16* xl    = sym_addr<__nv_bfloat16>(g_xl);
    __nv_bfloat16* hh    = sym_addr<__nv_bfloat16>(g_hh);
    __nv_bfloat16* hl    = sym_addr<__nv_bfloat16>(g_hl);
    __nv_bfloat16* wfh   = sym_addr<__nv_bfloat16>(g_wfh);
    __nv_bfloat16* wfl   = sym_addr<__nv_bfloat16>(g_wfl);
    __nv_bfloat16* fc1wh = sym_addr<__nv_bfloat16>(g_fc1wh);
    __nv_bfloat16* fc1wl = sym_addr<__nv_bfloat16>(g_fc1wl);
    __nv_bfloat16* fc2wh = sym_addr<__nv_bfloat16>(g_fc2wh);
    __nv_bfloat16* fc2wl = sym_addr<__nv_bfloat16>(g_fc2wl);
    __nv_bfloat16* embTh = sym_addr<__nv_bfloat16>(g_embTh);
    __nv_bfloat16* embTl = sym_addr<__nv_bfloat16>(g_embTl);
    __nv_bfloat16* psfh  = sym_addr<__nv_bfloat16>(g_psfh);
    __nv_bfloat16* psfl  = sym_addr<__nv_bfloat16>(g_psfl);
    __nv_bfloat16* fc1h  = sym_addr<__nv_bfloat16>(g_fc1h);
    __nv_bfloat16* fc1l  = sym_addr<__nv_bfloat16>(g_fc1l);
    __nv_bfloat16* e1h   = sym_addr<__nv_bfloat16>(g_e1h);
    __nv_bfloat16* e1l   = sym_addr<__nv_bfloat16>(g_e1l);

    const __nv_bfloat16* nbf = (const __nv_bfloat16*)nullptr;
    __nv_bfloat16* nbm = (__nv_bfloat16*)nullptr;
    const float* nf = (const float*)nullptr;

    static cudaStream_t s2 = nullptr, s3 = nullptr;
    static cudaEvent_t evF = nullptr, evG = nullptr, evL = nullptr, evP = nullptr;
    if (!s2){
        cudaStreamCreateWithFlags(&s2, cudaStreamNonBlocking);
        cudaStreamCreateWithFlags(&s3, cudaStreamNonBlocking);
        cudaEventCreateWithFlags(&evF, cudaEventDisableTiming);
        cudaEventCreateWithFlags(&evG, cudaEventDisableTiming);
        cudaEventCreateWithFlags(&evL, cudaEventDisableTiming);
        cudaEventCreateWithFlags(&evP, cudaEventDisableTiming);
    }

    cudaFuncSetAttribute(tgemm,  cudaFuncAttributeMaxDynamicSharedMemorySize, GSMEM);
    cudaFuncSetAttribute(tgemm3, cudaFuncAttributeMaxDynamicSharedMemorySize, GSMEM3);

    // ---- fork s3 from the origin stream FIRST (required for graph capture)
    cudaEventRecord(evF, 0);
    cudaStreamWaitEvent(s3, evF, 0);

    // ---- stream s3: input-only prologue -- fc2 weights, embT, svecs
    conv_kernel<<<(RP1*EE + 255)/256, 256, 0, s3>>>(fc2_w, fc2wh, fc2wl, RP1*EE);
    transpose_kernel<<<dim3(RS/32, EE/32), dim3(32, 8), 0, s3>>>(emb_w, embTh, embTl);
    svec_all_kernel<<<6, EE, 0, s3>>>(fc1_w, fc1_b, emb_w, svecs);
    cudaEventRecord(evP, s3);

    // ---- main stream: gather (needed by both branches), then fork s2
    gather_kernel<<<BB*LL, 64>>>(bodys, emb_w, xh, xl);
    cudaEventRecord(evG, 0);
    cudaStreamWaitEvent(s2, evG, 0);

    // ---- side stream s2: LSTM branch
    fusew_kernel<<<(4*EE*2*EE + 255)/256, 256, 0, s2>>>(w_ih, w_hh, wfh, wfl);
    bsum_kernel<<<1, 4*EE, 0, s2>>>(b_ih, b_hh, bsum);
    for (int t = 0; t < LL; t++){
        if (t == 0){
            tgemm<<<dim3(8, 8), 512, GSMEM, s2>>>(
                BB, 4*EE, EE,
                xh, xl, LL*EE, nbf, nbf, 0, EE,
                wfh + EE, wfl + EE, 2*EE,
                G, 4*EE, bsum, nf, 0, 0,
                nbm, nbm, 0);
        } else {
            tgemm<<<dim3(8, 8), 512, GSMEM, s2>>>(
                BB, 4*EE, 2*EE,
                hh, hl, EE,
                xh + (long long)t*EE, xl + (long long)t*EE, LL*EE, EE,
                wfh, wfl, 2*EE,
                G, 4*EE, bsum, nf, 0, 0,
                nbm, nbm, 0);
        }
        lstm_gates<<<(BB*EE + 255)/256, 256, 0, s2>>>(G, hh, hl, cbuf, hid, t);
    }
    cudaEventRecord(evL, s2);

    // ---- main stream: iteration 0
    conv_kernel<<<(EE*2*EE + 255)/256, 256>>>(fc1_w, fc1wh, fc1wl, EE*2*EE);
    tgemm<<<dim3(2, 8), 512, GSMEM>>>(
        BB, EE, 2*EE, xh, xl, LL*EE, nbf, nbf, 0, 2*EE,
        fc1wh, fc1wl, 2*EE,
        (float*)nullptr, 0, fc1_b, nf, 0, 1,
        fc1h, fc1l, EE);
    cudaStreamWaitEvent(0, evP, 0);
    tgemm3<<<dim3((RP1 + 127)/128, 16), 256, GSMEM3>>>(
        BB, RP1, EE, fc1h, fc1l, EE, fc2wh, fc2wl, EE,
        prob, RP1, fc2_b, (float*)nullptr, 0);
    softmax_kernel<<<BB, 256>>>(prob, psfh, psfl, plast);

    // ---- iterations 1..6
    for (int i = 1; i < LL - 1; i++){
        tgemm3<<<dim3(2, 16, NSPLIT), 256, GSMEM3>>>(
            BB, EE, RS, psfh, psfl, RS, embTh, embTl, RS,
            (float*)nullptr, 0, nf, part, KCH);

        if (i == 1) cudaStreamWaitEvent(0, evL, 0);   // join LSTM branch

        reduce_splitk<<<(BB*EE + 255)/256, 256>>>(
            part, emb1, e1h, e1l, hid + (long long)i*EE, plast);

        tgemm<<<dim3(2, 8), 512, GSMEM>>>(
            BB, EE, EE, e1h, e1l, EE, nbf, nbf, 0, EE,
            fc1wh, fc1wl, 2*EE,
            (float*)nullptr, 0, svecs + (long long)(i-1)*EE, nf, 0, 1,
            fc1h, fc1l, EE);

        tgemm3<<<dim3((RP1 + 127)/128, 16), 256, GSMEM3>>>(
            BB, RP1, EE, fc1h, fc1l, EE, fc2wh, fc2wl, EE,
            prob, RP1, fc2_b, (float*)nullptr, 0);

        if (i < LL - 2) softmax_kernel<<<BB, 256>>>(prob, psfh, psfl, plast);
    }

    if (out_size >= BB * RP1 + BB * 2 * EE)
        concat_kernel<<<(BB*2*EE + 255)/256, 256>>>(emb1, emb_w, outcat);
}